// round 8
// baseline (speedup 1.0000x reference)
#include <cuda_runtime.h>
#include <math.h>
#include <limits.h>

#define HDIM 128
#define SDIM 32
#define KTOP 8
#define RPB  128      // rows per block in K1
#define NBLK 782      // ceil(100000/128)

// Scratch (__device__ globals; no allocation allowed)
__device__ float g_cand_v[NBLK * KTOP];
__device__ int   g_cand_i[NBLK * KTOP];

__device__ __forceinline__ bool better(float va, int ia, float vb, int ib) {
    // jax.lax.top_k ordering: higher value first, ties -> lower index
    return (va > vb) || (va == vb && ia < ib);
}

__device__ __forceinline__ void insert_topk(float* lv, int* li, float v, int c) {
    if (better(v, c, lv[KTOP - 1], li[KTOP - 1])) {
        int j = KTOP - 1;
#pragma unroll
        for (; j > 0; --j) {
            if (better(v, c, lv[j - 1], li[j - 1])) {
                lv[j] = lv[j - 1];
                li[j] = li[j - 1];
            } else break;
        }
        lv[j] = v;
        li[j] = c;
    }
}

// ---------------------------------------------------------------------------
// K1: cosine sims (coalesced warp-per-row, 16 rows/warp) + block top-8.
// No global fence; candidates ordered by the kernel boundary.
// ---------------------------------------------------------------------------
__global__ void __launch_bounds__(256)
sims_topk(const float* __restrict__ q,
          const float* __restrict__ emb,
          int C) {
    __shared__ float sq[HDIM];
    __shared__ float s_rqn;
    __shared__ float s_sims[RPB];
    __shared__ float sv[16 * KTOP];
    __shared__ int   si[16 * KTOP];

    const int t    = threadIdx.x;
    const int lane = t & 31;
    const int w    = t >> 5;                  // warp 0..7

    if (t < HDIM) sq[t] = q[t];               // query row 0
    __syncthreads();
    if (t < 32) {
        const float4 a = reinterpret_cast<const float4*>(sq)[t];
        float s = a.x * a.x + a.y * a.y + a.z * a.z + a.w * a.w;
#pragma unroll
        for (int o = 16; o; o >>= 1) s += __shfl_xor_sync(0xffffffffu, s, o);
        if (t == 0) s_rqn = 1.0f / fmaxf(sqrtf(s), 1e-8f);
    }
    __syncthreads();
    const float rqn = s_rqn;
    const float4 q4 = reinterpret_cast<const float4*>(sq)[lane];

    const float4* __restrict__ emb4 = reinterpret_cast<const float4*>(emb);
    const int base = blockIdx.x * RPB;        // block's first row

    // Each warp streams 16 rows: 4 iterations of 4 front-batched coalesced loads.
#pragma unroll
    for (int it = 0; it < 4; ++it) {
        const int loc0 = w * 16 + it * 4;     // local row of j=0
        float4 ev[4];
#pragma unroll
        for (int j = 0; j < 4; ++j) {
            const int r = min(base + loc0 + j, C - 1);
            ev[j] = emb4[(size_t)r * (HDIM / 4) + lane];
        }
        float dot[4], esq[4];
#pragma unroll
        for (int j = 0; j < 4; ++j) {
            dot[j] = ev[j].x * q4.x + ev[j].y * q4.y + ev[j].z * q4.z + ev[j].w * q4.w;
            esq[j] = ev[j].x * ev[j].x + ev[j].y * ev[j].y + ev[j].z * ev[j].z + ev[j].w * ev[j].w;
        }
#pragma unroll
        for (int o = 16; o; o >>= 1) {
#pragma unroll
            for (int j = 0; j < 4; ++j) {
                dot[j] += __shfl_xor_sync(0xffffffffu, dot[j], o);
                esq[j] += __shfl_xor_sync(0xffffffffu, esq[j], o);
            }
        }
        if (lane < 4) {
            const int r = base + loc0 + lane;
            s_sims[loc0 + lane] = (r < C)
                ? dot[lane] * rqn / fmaxf(sqrtf(esq[lane]), 1e-8f)
                : -INFINITY;
        }
    }
    __syncthreads();

    // Block top-8 of 128 sims: 16 threads x 8 inserts, then 4-level merge tree.
    if (t < 16) {
        float lv[KTOP]; int li[KTOP];
#pragma unroll
        for (int j = 0; j < KTOP; ++j) { lv[j] = -INFINITY; li[j] = INT_MAX; }
#pragma unroll
        for (int j = 0; j < 8; ++j)
            insert_topk(lv, li, s_sims[t * 8 + j], base + t * 8 + j);
#pragma unroll
        for (int j = 0; j < KTOP; ++j) { sv[t * KTOP + j] = lv[j]; si[t * KTOP + j] = li[j]; }
    }
    __syncthreads();
    for (int s = 8; s > 0; s >>= 1) {
        if (t < s) {
            float mv[KTOP]; int mi[KTOP];
            int a = 0, b = 0;
#pragma unroll
            for (int j = 0; j < KTOP; ++j) {
                const float va = sv[t * KTOP + a];       const int ia = si[t * KTOP + a];
                const float vb = sv[(t + s) * KTOP + b]; const int ib = si[(t + s) * KTOP + b];
                if (better(va, ia, vb, ib)) { mv[j] = va; mi[j] = ia; ++a; }
                else                        { mv[j] = vb; mi[j] = ib; ++b; }
            }
#pragma unroll
            for (int j = 0; j < KTOP; ++j) { sv[t * KTOP + j] = mv[j]; si[t * KTOP + j] = mi[j]; }
        }
        __syncthreads();
    }
    if (t < KTOP) {
        g_cand_v[blockIdx.x * KTOP + t] = sv[t];
        g_cand_i[blockIdx.x * KTOP + t] = si[t];
    }
}

// ---------------------------------------------------------------------------
// K2: merge NBLK*KTOP = 6256 candidates -> global top-8, gather episodes,
// write scores. One block, 1024 threads (threads 0..255 do the merge).
// ---------------------------------------------------------------------------
__global__ void __launch_bounds__(1024)
final_gather(const float* __restrict__ episodes,
             float* __restrict__ out) {
    __shared__ float sv[256 * KTOP];
    __shared__ int   si[256 * KTOP];
    const int t = threadIdx.x;

    if (t < 256) {
        float lv[KTOP]; int li[KTOP];
#pragma unroll
        for (int j = 0; j < KTOP; ++j) { lv[j] = -INFINITY; li[j] = INT_MAX; }
        for (int c = t; c < NBLK * KTOP; c += 256)
            insert_topk(lv, li, g_cand_v[c], g_cand_i[c]);
#pragma unroll
        for (int j = 0; j < KTOP; ++j) { sv[t * KTOP + j] = lv[j]; si[t * KTOP + j] = li[j]; }
    }
    __syncthreads();

    for (int s = 128; s > 0; s >>= 1) {
        if (t < s) {
            float mv[KTOP]; int mi[KTOP];
            int a = 0, b = 0;
#pragma unroll
            for (int j = 0; j < KTOP; ++j) {
                const float va = sv[t * KTOP + a];       const int ia = si[t * KTOP + a];
                const float vb = sv[(t + s) * KTOP + b]; const int ib = si[(t + s) * KTOP + b];
                if (better(va, ia, vb, ib)) { mv[j] = va; mi[j] = ia; ++a; }
                else                        { mv[j] = vb; mi[j] = ib; ++b; }
            }
#pragma unroll
            for (int j = 0; j < KTOP; ++j) { sv[t * KTOP + j] = mv[j]; si[t * KTOP + j] = mi[j]; }
        }
        __syncthreads();
    }
    // global top-8 in sv[0..7] / si[0..7]

    // Gather 8 episodes [8,32,128]: 8192 float4, 8 independent per thread.
    const float4* __restrict__ epi4 = reinterpret_cast<const float4*>(episodes);
    float4* __restrict__ out4 = reinterpret_cast<float4*>(out);
#pragma unroll
    for (int r = 0; r < 8; ++r) {
        const int j   = r * 1024 + t;          // 0..8191
        const int e   = j >> 10;               // episode slot (1024 float4 each)
        const int off = j & 1023;
        const int idx = si[e];
        out4[j] = epi4[(size_t)idx * (SDIM * HDIM / 4) + off];
    }
    if (t < KTOP)
        out[KTOP * SDIM * HDIM + t] = sv[t];   // top_scores[0]
}

extern "C" void kernel_launch(void* const* d_in, const int* in_sizes, int n_in,
                              void* d_out, int out_size) {
    const float* query    = (const float*)d_in[0];  // [B, 128]
    const float* episodes = (const float*)d_in[1];  // [C, 32, 128]
    const float* emb      = (const float*)d_in[2];  // [C, 128]
    (void)n_in; (void)out_size;

    const int C = in_sizes[2] / HDIM;               // 100000
    const int nblk = (C + RPB - 1) / RPB;           // 782

    sims_topk<<<nblk, 256>>>(query, emb, C);
    final_gather<<<1, 1024>>>(episodes, (float*)d_out);
}

// round 9
// speedup vs baseline: 1.2958x; 1.2958x over previous
#include <cuda_runtime.h>
#include <math.h>
#include <limits.h>

#define HDIM 128
#define SDIM 32
#define KTOP 8
#define RPB  128                  // rows per block in K1
#define NBLK 782                  // ceil(100000/128)
#define NCAND (NBLK * KTOP)       // 6256
#define MT   512                  // merge threads in K2
#define CPT  13                   // ceil(NCAND/MT)

// Scratch (__device__ globals; no allocation allowed)
__device__ float2 g_cand[NBLK * KTOP];   // (value, index bits)

__device__ __forceinline__ bool better(float va, int ia, float vb, int ib) {
    // jax.lax.top_k ordering: higher value first, ties -> lower index
    return (va > vb) || (va == vb && ia < ib);
}

__device__ __forceinline__ bool better2(float2 a, float2 b) {
    return (a.x > b.x) ||
           (a.x == b.x && __float_as_int(a.y) < __float_as_int(b.y));
}

__device__ __forceinline__ void insert_topk(float* lv, int* li, float v, int c) {
    if (better(v, c, lv[KTOP - 1], li[KTOP - 1])) {
        int j = KTOP - 1;
#pragma unroll
        for (; j > 0; --j) {
            if (better(v, c, lv[j - 1], li[j - 1])) {
                lv[j] = lv[j - 1];
                li[j] = li[j - 1];
            } else break;
        }
        lv[j] = v;
        li[j] = c;
    }
}

__device__ __forceinline__ void insert2(float2* ls, float2 v) {
    if (better2(v, ls[KTOP - 1])) {
        int j = KTOP - 1;
#pragma unroll
        for (; j > 0; --j) {
            if (better2(v, ls[j - 1])) ls[j] = ls[j - 1];
            else break;
        }
        ls[j] = v;
    }
}

// ---------------------------------------------------------------------------
// K1: cosine sims (coalesced warp-per-row, 16 rows/warp) + block top-8.
// ---------------------------------------------------------------------------
__global__ void __launch_bounds__(256)
sims_topk(const float* __restrict__ q,
          const float* __restrict__ emb,
          int C) {
    __shared__ float sq[HDIM];
    __shared__ float s_rqn;
    __shared__ float s_sims[RPB];
    __shared__ float sv[16 * KTOP];
    __shared__ int   si[16 * KTOP];

    const int t    = threadIdx.x;
    const int lane = t & 31;
    const int w    = t >> 5;

    if (t < HDIM) sq[t] = q[t];               // query row 0
    __syncthreads();
    if (t < 32) {
        const float4 a = reinterpret_cast<const float4*>(sq)[t];
        float s = a.x * a.x + a.y * a.y + a.z * a.z + a.w * a.w;
#pragma unroll
        for (int o = 16; o; o >>= 1) s += __shfl_xor_sync(0xffffffffu, s, o);
        if (t == 0) s_rqn = 1.0f / fmaxf(sqrtf(s), 1e-8f);
    }
    __syncthreads();
    const float rqn = s_rqn;
    const float4 q4 = reinterpret_cast<const float4*>(sq)[lane];

    const float4* __restrict__ emb4 = reinterpret_cast<const float4*>(emb);
    const int base = blockIdx.x * RPB;

#pragma unroll
    for (int it = 0; it < 4; ++it) {
        const int loc0 = w * 16 + it * 4;
        float4 ev[4];
#pragma unroll
        for (int j = 0; j < 4; ++j) {
            const int r = min(base + loc0 + j, C - 1);
            ev[j] = emb4[(size_t)r * (HDIM / 4) + lane];
        }
        float dot[4], esq[4];
#pragma unroll
        for (int j = 0; j < 4; ++j) {
            dot[j] = ev[j].x * q4.x + ev[j].y * q4.y + ev[j].z * q4.z + ev[j].w * q4.w;
            esq[j] = ev[j].x * ev[j].x + ev[j].y * ev[j].y + ev[j].z * ev[j].z + ev[j].w * ev[j].w;
        }
#pragma unroll
        for (int o = 16; o; o >>= 1) {
#pragma unroll
            for (int j = 0; j < 4; ++j) {
                dot[j] += __shfl_xor_sync(0xffffffffu, dot[j], o);
                esq[j] += __shfl_xor_sync(0xffffffffu, esq[j], o);
            }
        }
        if (lane < 4) {
            const int r = base + loc0 + lane;
            s_sims[loc0 + lane] = (r < C)
                ? dot[lane] * rqn / fmaxf(sqrtf(esq[lane]), 1e-8f)
                : -INFINITY;
        }
    }
    __syncthreads();

    // Block top-8 of 128 sims: 16 threads x 8 inserts, then 4-level merge.
    if (t < 16) {
        float lv[KTOP]; int li[KTOP];
#pragma unroll
        for (int j = 0; j < KTOP; ++j) { lv[j] = -INFINITY; li[j] = INT_MAX; }
#pragma unroll
        for (int j = 0; j < 8; ++j)
            insert_topk(lv, li, s_sims[t * 8 + j], base + t * 8 + j);
#pragma unroll
        for (int j = 0; j < KTOP; ++j) { sv[t * KTOP + j] = lv[j]; si[t * KTOP + j] = li[j]; }
    }
    __syncthreads();
    for (int s = 8; s > 0; s >>= 1) {
        if (t < s) {
            float mv[KTOP]; int mi[KTOP];
            int a = 0, b = 0;
#pragma unroll
            for (int j = 0; j < KTOP; ++j) {
                const float va = sv[t * KTOP + a];       const int ia = si[t * KTOP + a];
                const float vb = sv[(t + s) * KTOP + b]; const int ib = si[(t + s) * KTOP + b];
                if (better(va, ia, vb, ib)) { mv[j] = va; mi[j] = ia; ++a; }
                else                        { mv[j] = vb; mi[j] = ib; ++b; }
            }
#pragma unroll
            for (int j = 0; j < KTOP; ++j) { sv[t * KTOP + j] = mv[j]; si[t * KTOP + j] = mi[j]; }
        }
        __syncthreads();
    }
    if (t < KTOP)
        g_cand[blockIdx.x * KTOP + t] = make_float2(sv[t], __int_as_float(si[t]));
}

// ---------------------------------------------------------------------------
// K2: merge 6256 candidates -> global top-8 (front-batched loads, 9-level
// tree), then 1024-thread gather + scores. One block.
// ---------------------------------------------------------------------------
__global__ void __launch_bounds__(1024)
final_gather(const float* __restrict__ episodes,
             float* __restrict__ out) {
    __shared__ float2 sc[MT * KTOP];          // 32 KB
    const int t = threadIdx.x;

    if (t < MT) {
        // Front-batched candidate loads: CPT independent predicated LDG.64.
        float2 cd[CPT];
#pragma unroll
        for (int r = 0; r < CPT; ++r) {
            const int c = t + r * MT;
            cd[r] = (c < NCAND) ? g_cand[c]
                                : make_float2(-INFINITY, __int_as_float(INT_MAX));
        }
        // ALU-only local top-8.
        float2 ls[KTOP];
#pragma unroll
        for (int j = 0; j < KTOP; ++j)
            ls[j] = make_float2(-INFINITY, __int_as_float(INT_MAX));
#pragma unroll
        for (int r = 0; r < CPT; ++r) insert2(ls, cd[r]);
#pragma unroll
        for (int j = 0; j < KTOP; ++j) sc[t * KTOP + j] = ls[j];
    }
    __syncthreads();

    // 9-level merge tree: 512 sorted lists -> 1.
    for (int s = MT / 2; s > 0; s >>= 1) {
        if (t < s) {
            float2 m[KTOP];
            int a = 0, b = 0;
#pragma unroll
            for (int j = 0; j < KTOP; ++j) {
                const float2 va = sc[t * KTOP + a];
                const float2 vb = sc[(t + s) * KTOP + b];
                if (better2(va, vb)) { m[j] = va; ++a; }
                else                 { m[j] = vb; ++b; }
            }
#pragma unroll
            for (int j = 0; j < KTOP; ++j) sc[t * KTOP + j] = m[j];
        }
        __syncthreads();
    }
    // global top-8 in sc[0..7]

    // Gather: thread t handles float4 column t of each of the 8 episodes.
    // All 8 loads are independent and front-batched.
    const float4* __restrict__ epi4 = reinterpret_cast<const float4*>(episodes);
    float4* __restrict__ out4 = reinterpret_cast<float4*>(out);
    float4 vals[KTOP];
#pragma unroll
    for (int e = 0; e < KTOP; ++e) {
        const int idx = __float_as_int(sc[e].y);
        vals[e] = epi4[(size_t)idx * (SDIM * HDIM / 4) + t];
    }
#pragma unroll
    for (int e = 0; e < KTOP; ++e)
        out4[e * (SDIM * HDIM / 4) + t] = vals[e];

    if (t < KTOP)
        out[KTOP * SDIM * HDIM + t] = sc[t].x;   // top_scores[0]
}

extern "C" void kernel_launch(void* const* d_in, const int* in_sizes, int n_in,
                              void* d_out, int out_size) {
    const float* query    = (const float*)d_in[0];  // [B, 128]
    const float* episodes = (const float*)d_in[1];  // [C, 32, 128]
    const float* emb      = (const float*)d_in[2];  // [C, 128]
    (void)n_in; (void)out_size;

    const int C = in_sizes[2] / HDIM;               // 100000
    const int nblk = (C + RPB - 1) / RPB;           // 782

    sims_topk<<<nblk, 256>>>(query, emb, C);
    final_gather<<<1, 1024>>>(episodes, (float*)d_out);
}